// round 2
// baseline (speedup 1.0000x reference)
#include <cuda_runtime.h>
#include <math.h>

#define NRAYS 8192
#define NS    128
#define NC    32
#define NH    64
#define NG    128

// dynamic smem layout (in floats)
#define OFF_WT1   0        // 32*64 = 2048
#define OFF_WT2   2048     // 64*64 = 4096
#define OFF_WO1   6144     // 4096
#define OFF_WC1   10240    // 4096
#define OFF_WO2   14336    // 64
#define OFF_WC2   14400    // 192
#define OFF_BT1   14592    // 64
#define OFF_BT2   14656    // 64
#define OFF_BO1   14720    // 64
#define OFF_BC1   14784    // 64
#define OFF_RAY   14848    // 64
#define OFF_HE    14912    // 21 (pad to 24)
#define OFF_DIR   14936    // 3
#define OFF_BO2   14939    // 1
#define OFF_BC2   14940    // 3 (pad 1)
#define OFF_AM    14944    // 128
#define OFF_T     15072    // 129
#define OFF_PART  15204    // 12  (aligned to 4)
#define SMEM_FLOATS 15216
#define SMEM_BYTES (SMEM_FLOATS * 4)

__device__ __forceinline__ float frelu(float x) { return x > 0.f ? x : 0.f; }

// out[64] = in[IN] @ W[IN,64] + b[64]; W,b in shared, in/out in registers.
template <int IN>
__device__ __forceinline__ void dense64(const float* in, const float* sW,
                                        const float* sb, float* acc) {
#pragma unroll
    for (int o = 0; o < 16; o++) {
        float4 b4 = ((const float4*)sb)[o];
        acc[4 * o + 0] = b4.x; acc[4 * o + 1] = b4.y;
        acc[4 * o + 2] = b4.z; acc[4 * o + 3] = b4.w;
    }
#pragma unroll
    for (int i = 0; i < IN; i++) {
        float f = in[i];
        const float4* w4 = (const float4*)(sW + i * NH);
#pragma unroll
        for (int o = 0; o < 16; o++) {
            float4 w = w4[o];
            acc[4 * o + 0] = fmaf(f, w.x, acc[4 * o + 0]);
            acc[4 * o + 1] = fmaf(f, w.y, acc[4 * o + 1]);
            acc[4 * o + 2] = fmaf(f, w.z, acc[4 * o + 2]);
            acc[4 * o + 3] = fmaf(f, w.w, acc[4 * o + 3]);
        }
    }
}

__global__ void __launch_bounds__(NS)
lightplane_kernel(const float* __restrict__ origins,
                  const float* __restrict__ directions,
                  const float* __restrict__ nearv,
                  const float* __restrict__ farv,
                  const float* __restrict__ grid,
                  const float* __restrict__ Wr,  const float* __restrict__ br,
                  const float* __restrict__ Wt1, const float* __restrict__ bt1,
                  const float* __restrict__ Wt2, const float* __restrict__ bt2,
                  const float* __restrict__ Wo1, const float* __restrict__ bo1,
                  const float* __restrict__ Wo2, const float* __restrict__ bo2,
                  const float* __restrict__ Wc1, const float* __restrict__ bc1,
                  const float* __restrict__ Wc2, const float* __restrict__ bc2,
                  float* __restrict__ out) {
    extern __shared__ float sm[];
    const int tid = threadIdx.x;
    const int ray = blockIdx.x;

    // ---- stage weights into shared ----
    {
        const float4* g;
        float4* s;
        g = (const float4*)Wt1; s = (float4*)(sm + OFF_WT1);
        for (int i = tid; i < 512; i += NS) s[i] = g[i];
        g = (const float4*)Wt2; s = (float4*)(sm + OFF_WT2);
        for (int i = tid; i < 1024; i += NS) s[i] = g[i];
        g = (const float4*)Wo1; s = (float4*)(sm + OFF_WO1);
        for (int i = tid; i < 1024; i += NS) s[i] = g[i];
        g = (const float4*)Wc1; s = (float4*)(sm + OFF_WC1);
        for (int i = tid; i < 1024; i += NS) s[i] = g[i];
        if (tid < 16)  ((float4*)(sm + OFF_WO2))[tid] = ((const float4*)Wo2)[tid];
        if (tid < 48)  ((float4*)(sm + OFF_WC2))[tid] = ((const float4*)Wc2)[tid];
        if (tid < 16)  ((float4*)(sm + OFF_BT1))[tid] = ((const float4*)bt1)[tid];
        if (tid >= 16 && tid < 32) ((float4*)(sm + OFF_BT2))[tid - 16] = ((const float4*)bt2)[tid - 16];
        if (tid >= 32 && tid < 48) ((float4*)(sm + OFF_BO1))[tid - 32] = ((const float4*)bo1)[tid - 32];
        if (tid >= 48 && tid < 64) ((float4*)(sm + OFF_BC1))[tid - 48] = ((const float4*)bc1)[tid - 48];
        if (tid == 64) sm[OFF_BO2] = bo2[0];
        if (tid >= 65 && tid < 68) sm[OFF_BC2 + tid - 65] = bc2[tid - 65];
        if (tid >= 68 && tid < 71) sm[OFF_DIR + tid - 68] = directions[ray * 3 + (tid - 68)];
    }
    __syncthreads();

    // ---- harmonic ray encoding (per ray) ----
    if (tid < 9) {
        int f = tid / 3, d = tid % 3;
        float ang = sm[OFF_DIR + d] * (float)(1 << f);
        sm[OFF_HE + tid]     = sinf(ang);
        sm[OFF_HE + 9 + tid] = cosf(ang);
    }
    if (tid >= 9 && tid < 12) sm[OFF_HE + 9 + tid] = sm[OFF_DIR + tid - 9];  // he[18..20]=dir
    __syncthreads();
    if (tid < NH) {
        float acc = br[tid];
#pragma unroll
        for (int k = 0; k < 21; k++) acc = fmaf(sm[OFF_HE + k], Wr[k * NH + tid], acc);
        sm[OFF_RAY + tid] = acc;
    }
    __syncthreads();

    // ---- per-sample work (thread = sample) ----
    const float nr = nearv[ray];
    const float fa = farv[ray];
    const float dx = sm[OFF_DIR + 0], dy = sm[OFF_DIR + 1], dz = sm[OFF_DIR + 2];
    const float ox = origins[ray * 3 + 0], oy = origins[ray * 3 + 1], oz = origins[ray * 3 + 2];

    const float t = nr + (fa - nr) * (((float)tid + 0.5f) / (float)NS);
    const float px = ox + t * dx;
    const float py = oy + t * dy;
    const float pz = oz + t * dz;

    // trilinear interpolation of 32-ch features
    float feats[NC];
#pragma unroll
    for (int q = 0; q < NC; q++) feats[q] = 0.f;
    {
        const float scale = 0.5f * (float)(NG - 1);
        float cx = (px + 1.f) * scale;
        float cy = (py + 1.f) * scale;
        float cz = (pz + 1.f) * scale;
        float fx = cx - floorf(cx), fy = cy - floorf(cy), fz = cz - floorf(cz);
        int x0 = min(max((int)floorf(cx), 0), NG - 1);
        int y0 = min(max((int)floorf(cy), 0), NG - 1);
        int z0 = min(max((int)floorf(cz), 0), NG - 1);
        int x1 = min(x0 + 1, NG - 1);
        int y1 = min(y0 + 1, NG - 1);
        int z1 = min(z0 + 1, NG - 1);
        float wx[2] = {1.f - fx, fx};
        float wy[2] = {1.f - fy, fy};
        float wz[2] = {1.f - fz, fz};
        int xs[2] = {x0, x1}, ys[2] = {y0, y1}, zs[2] = {z0, z1};
#pragma unroll
        for (int a = 0; a < 2; a++)
#pragma unroll
            for (int b = 0; b < 2; b++)
#pragma unroll
                for (int c = 0; c < 2; c++) {
                    float w = wx[a] * wy[b] * wz[c];
                    const float4* g4 = (const float4*)(grid +
                        ((size_t)((zs[c] * NG + ys[b]) * NG + xs[a])) * NC);
#pragma unroll
                    for (int q = 0; q < 8; q++) {
                        float4 v = __ldg(&g4[q]);
                        feats[4 * q + 0] = fmaf(w, v.x, feats[4 * q + 0]);
                        feats[4 * q + 1] = fmaf(w, v.y, feats[4 * q + 1]);
                        feats[4 * q + 2] = fmaf(w, v.z, feats[4 * q + 2]);
                        feats[4 * q + 3] = fmaf(w, v.w, feats[4 * q + 3]);
                    }
                }
    }

    // MLP trunk: e = relu(relu(feats@Wt1+bt1)@Wt2+bt2)
    float e1[NH];
    dense64<NC>(feats, sm + OFF_WT1, sm + OFF_BT1, e1);
#pragma unroll
    for (int o = 0; o < NH; o++) e1[o] = frelu(e1[o]);
    float e[NH];
    dense64<NH>(e1, sm + OFF_WT2, sm + OFF_BT2, e);
#pragma unroll
    for (int o = 0; o < NH; o++) e[o] = frelu(e[o]);

    // opacity head: raw = relu(e@Wo1+bo1)@Wo2 + bo2
    float h[NH];
    dense64<NH>(e, sm + OFF_WO1, sm + OFF_BO1, h);
    float raw = sm[OFF_BO2];
#pragma unroll
    for (int i = 0; i < NH; i++) raw = fmaf(frelu(h[i]), sm[OFF_WO2 + i], raw);

    // density -> alpha
    float density = (raw > 0.f) ? (raw + log1pf(expf(-raw))) : log1pf(expf(raw));
    float delta = (fa - nr) / (float)NS;
    float am = expf(-delta * density);   // 1 - alpha
    sm[OFF_AM + tid] = am;

    // color head: col = sigmoid(relu((e+ray_enc)@Wc1+bc1)@Wc2+bc2)
#pragma unroll
    for (int i = 0; i < NH; i++) e[i] += sm[OFF_RAY + i];
    dense64<NH>(e, sm + OFF_WC1, sm + OFF_BC1, h);
    float c0 = sm[OFF_BC2 + 0], c1 = sm[OFF_BC2 + 1], c2 = sm[OFF_BC2 + 2];
#pragma unroll
    for (int i = 0; i < NH; i++) {
        float hv = frelu(h[i]);
        c0 = fmaf(hv, sm[OFF_WC2 + i * 3 + 0], c0);
        c1 = fmaf(hv, sm[OFF_WC2 + i * 3 + 1], c1);
        c2 = fmaf(hv, sm[OFF_WC2 + i * 3 + 2], c2);
    }
    c0 = 1.f / (1.f + expf(-c0));
    c1 = 1.f / (1.f + expf(-c1));
    c2 = 1.f / (1.f + expf(-c2));

    // ---- transmittance scan ----
    __syncthreads();
    if (tid == 0) {
        float T = 1.f;
#pragma unroll 1
        for (int s = 0; s < NS; s++) { sm[OFF_T + s] = T; T *= sm[OFF_AM + s]; }
        sm[OFF_T + NS] = T;
    }
    __syncthreads();

    float wgt = sm[OFF_T + tid] * (1.f - am);
    float r0 = wgt * c0, r1 = wgt * c1, r2 = wgt * c2;
#pragma unroll
    for (int off = 16; off > 0; off >>= 1) {
        r0 += __shfl_down_sync(0xffffffffu, r0, off);
        r1 += __shfl_down_sync(0xffffffffu, r1, off);
        r2 += __shfl_down_sync(0xffffffffu, r2, off);
    }
    const int warp = tid >> 5, lane = tid & 31;
    if (lane == 0) {
        sm[OFF_PART + warp * 3 + 0] = r0;
        sm[OFF_PART + warp * 3 + 1] = r1;
        sm[OFF_PART + warp * 3 + 2] = r2;
    }
    __syncthreads();
    if (tid == 0) {
        float s0 = 0.f, s1 = 0.f, s2 = 0.f;
#pragma unroll
        for (int w = 0; w < 4; w++) {
            s0 += sm[OFF_PART + w * 3 + 0];
            s1 += sm[OFF_PART + w * 3 + 1];
            s2 += sm[OFF_PART + w * 3 + 2];
        }
        out[ray * 3 + 0] = s0;
        out[ray * 3 + 1] = s1;
        out[ray * 3 + 2] = s2;
        out[NRAYS * 3 + ray] = 1.f - sm[OFF_T + NS];   // mask
    }
}

extern "C" void kernel_launch(void* const* d_in, const int* in_sizes, int n_in,
                              void* d_out, int out_size) {
    const float* origins    = (const float*)d_in[0];
    const float* directions = (const float*)d_in[1];
    const float* nearv      = (const float*)d_in[2];
    const float* farv       = (const float*)d_in[3];
    const float* grid       = (const float*)d_in[4];
    const float* Wr  = (const float*)d_in[5];
    const float* br  = (const float*)d_in[6];
    const float* Wt1 = (const float*)d_in[7];
    const float* bt1 = (const float*)d_in[8];
    const float* Wt2 = (const float*)d_in[9];
    const float* bt2 = (const float*)d_in[10];
    const float* Wo1 = (const float*)d_in[11];
    const float* bo1 = (const float*)d_in[12];
    const float* Wo2 = (const float*)d_in[13];
    const float* bo2 = (const float*)d_in[14];
    const float* Wc1 = (const float*)d_in[15];
    const float* bc1 = (const float*)d_in[16];
    const float* Wc2 = (const float*)d_in[17];
    const float* bc2 = (const float*)d_in[18];
    float* out = (float*)d_out;

    cudaFuncSetAttribute(lightplane_kernel,
                         cudaFuncAttributeMaxDynamicSharedMemorySize, SMEM_BYTES);
    lightplane_kernel<<<NRAYS, NS, SMEM_BYTES>>>(
        origins, directions, nearv, farv, grid,
        Wr, br, Wt1, bt1, Wt2, bt2, Wo1, bo1, Wo2, bo2,
        Wc1, bc1, Wc2, bc2, out);
}

// round 3
// speedup vs baseline: 1.4286x; 1.4286x over previous
#include <cuda_runtime.h>
#include <math.h>

#define NRAYS 8192
#define NS    128
#define NC    32
#define NH    64
#define NG    128
#define RPB   8          // rays per block

// dynamic smem layout (float offsets)
#define OFF_WT1   0        // 2048
#define OFF_WT2   2048     // 4096
#define OFF_WO1   6144     // 4096
#define OFF_WC1   10240    // 4096
#define OFF_WR    14336    // 21*64 = 1344
#define OFF_WO2   15680    // 64
#define OFF_WC2   15744    // 192
#define OFF_BT1   15936    // 64
#define OFF_BT2   16000    // 64
#define OFF_BO1   16064    // 64
#define OFF_BC1   16128    // 64
#define OFF_BR    16192    // 64
#define OFF_RAY   16256    // 64
#define OFF_HE    16320    // 21 (pad 24)
#define OFF_WTOT  16344    // 4
#define OFF_PART  16348    // 12
#define OFF_MISC  16360    // bo2 (1) + bc2 (3)
#define SMEM_FLOATS 16364
#define SMEM_BYTES (SMEM_FLOATS * 4)

__device__ __forceinline__ float frelu(float x) { return x > 0.f ? x : 0.f; }

__device__ __forceinline__ unsigned long long pack2(float a) {
    unsigned long long r;
    unsigned u = __float_as_uint(a);
    asm("mov.b64 %0, {%1, %1};" : "=l"(r) : "r"(u));
    return r;
}

__device__ __forceinline__ void fma2(unsigned long long& d,
                                     unsigned long long a,
                                     unsigned long long b) {
    asm("fma.rn.f32x2 %0, %1, %2, %0;" : "+l"(d) : "l"(a), "l"(b));
}

__device__ __forceinline__ void unpack2(unsigned long long v, float& lo, float& hi) {
    unsigned l, h;
    asm("mov.b64 {%0, %1}, %2;" : "=r"(l), "=r"(h) : "l"(v));
    lo = __uint_as_float(l);
    hi = __uint_as_float(h);
}

// outv[64] = in[IN] @ W[IN,64] + b[64]; W,b in shared. Packed f32x2 (FFMA2).
template <int IN>
__device__ __forceinline__ void dense64p(const float* in, const float* sW,
                                         const float* sb, float* outv) {
    unsigned long long acc[32];
    const ulonglong2* b2 = (const ulonglong2*)sb;
#pragma unroll
    for (int o = 0; o < 16; o++) {
        ulonglong2 b = b2[o];
        acc[2 * o] = b.x;
        acc[2 * o + 1] = b.y;
    }
#pragma unroll
    for (int i = 0; i < IN; i++) {
        unsigned long long f2 = pack2(in[i]);
        const ulonglong2* w2 = (const ulonglong2*)(sW + i * NH);
#pragma unroll
        for (int o = 0; o < 16; o++) {
            ulonglong2 w = w2[o];
            fma2(acc[2 * o], f2, w.x);
            fma2(acc[2 * o + 1], f2, w.y);
        }
    }
#pragma unroll
    for (int o = 0; o < 32; o++) unpack2(acc[o], outv[2 * o], outv[2 * o + 1]);
}

__global__ void __launch_bounds__(NS, 2)
lightplane_kernel(const float* __restrict__ origins,
                  const float* __restrict__ directions,
                  const float* __restrict__ nearv,
                  const float* __restrict__ farv,
                  const float* __restrict__ grid,
                  const float* __restrict__ Wr,  const float* __restrict__ br,
                  const float* __restrict__ Wt1, const float* __restrict__ bt1,
                  const float* __restrict__ Wt2, const float* __restrict__ bt2,
                  const float* __restrict__ Wo1, const float* __restrict__ bo1,
                  const float* __restrict__ Wo2, const float* __restrict__ bo2,
                  const float* __restrict__ Wc1, const float* __restrict__ bc1,
                  const float* __restrict__ Wc2, const float* __restrict__ bc2,
                  float* __restrict__ out) {
    extern __shared__ float sm[];
    const int tid = threadIdx.x;
    const int lane = tid & 31;
    const int warp = tid >> 5;

    // ---- stage all weights into shared (once per block) ----
    {
        const float4* g;
        float4* s;
        g = (const float4*)Wt1; s = (float4*)(sm + OFF_WT1);
        for (int i = tid; i < 512; i += NS) s[i] = g[i];
        g = (const float4*)Wt2; s = (float4*)(sm + OFF_WT2);
        for (int i = tid; i < 1024; i += NS) s[i] = g[i];
        g = (const float4*)Wo1; s = (float4*)(sm + OFF_WO1);
        for (int i = tid; i < 1024; i += NS) s[i] = g[i];
        g = (const float4*)Wc1; s = (float4*)(sm + OFF_WC1);
        for (int i = tid; i < 1024; i += NS) s[i] = g[i];
        g = (const float4*)Wr; s = (float4*)(sm + OFF_WR);
        for (int i = tid; i < 336; i += NS) s[i] = g[i];
        if (tid < 16)              ((float4*)(sm + OFF_WO2))[tid]      = ((const float4*)Wo2)[tid];
        if (tid < 48)              ((float4*)(sm + OFF_WC2))[tid]      = ((const float4*)Wc2)[tid];
        if (tid >= 48 && tid < 64) ((float4*)(sm + OFF_BT1))[tid - 48] = ((const float4*)bt1)[tid - 48];
        if (tid >= 64 && tid < 80) ((float4*)(sm + OFF_BT2))[tid - 64] = ((const float4*)bt2)[tid - 64];
        if (tid >= 80 && tid < 96) ((float4*)(sm + OFF_BO1))[tid - 80] = ((const float4*)bo1)[tid - 80];
        if (tid >= 96 && tid < 112)((float4*)(sm + OFF_BC1))[tid - 96] = ((const float4*)bc1)[tid - 96];
        if (tid >= 112 && tid < 128)((float4*)(sm + OFF_BR))[tid - 112]= ((const float4*)br)[tid - 112];
        if (tid == 16) sm[OFF_MISC] = bo2[0];
        if (tid >= 17 && tid < 20) sm[OFF_MISC + 1 + tid - 17] = bc2[tid - 17];
    }
    __syncthreads();

    for (int rr = 0; rr < RPB; rr++) {
        const int ray = blockIdx.x * RPB + rr;
        const float dx = directions[ray * 3 + 0];
        const float dy = directions[ray * 3 + 1];
        const float dz = directions[ray * 3 + 2];
        const float nr = nearv[ray];
        const float fa = farv[ray];
        const float ox = origins[ray * 3 + 0];
        const float oy = origins[ray * 3 + 1];
        const float oz = origins[ray * 3 + 2];

        // harmonic encoding of direction (per ray)
        if (tid < 9) {
            int f = tid / 3, d = tid % 3;
            float dv = (d == 0) ? dx : ((d == 1) ? dy : dz);
            float ang = dv * (float)(1 << f);
            sm[OFF_HE + tid]     = sinf(ang);
            sm[OFF_HE + 9 + tid] = cosf(ang);
        }
        if (tid >= 9 && tid < 12) {
            int d = tid - 9;
            sm[OFF_HE + 18 + d] = (d == 0) ? dx : ((d == 1) ? dy : dz);
        }
        __syncthreads();                      // sync1: HE ready
        if (tid < NH) {
            float a = sm[OFF_BR + tid];
#pragma unroll
            for (int k = 0; k < 21; k++)
                a = fmaf(sm[OFF_HE + k], sm[OFF_WR + k * NH + tid], a);
            sm[OFF_RAY + tid] = a;
        }

        // ---- per-sample (thread = sample) ----
        const float t = nr + (fa - nr) * (((float)tid + 0.5f) / (float)NS);
        const float px = ox + t * dx;
        const float py = oy + t * dy;
        const float pz = oz + t * dz;

        // trilinear gather of 32-channel features (packed accumulation)
        float feats[NC];
        {
            unsigned long long fa2[16];
#pragma unroll
            for (int q = 0; q < 16; q++) fa2[q] = 0ull;
            const float scale = 0.5f * (float)(NG - 1);
            float cx = (px + 1.f) * scale;
            float cy = (py + 1.f) * scale;
            float cz = (pz + 1.f) * scale;
            float fx = cx - floorf(cx), fy = cy - floorf(cy), fz = cz - floorf(cz);
            int x0 = min(max((int)floorf(cx), 0), NG - 1);
            int y0 = min(max((int)floorf(cy), 0), NG - 1);
            int z0 = min(max((int)floorf(cz), 0), NG - 1);
            int x1 = min(x0 + 1, NG - 1);
            int y1 = min(y0 + 1, NG - 1);
            int z1 = min(z0 + 1, NG - 1);
            float wx[2] = {1.f - fx, fx};
            float wy[2] = {1.f - fy, fy};
            float wz[2] = {1.f - fz, fz};
            int xs[2] = {x0, x1}, ys[2] = {y0, y1}, zs[2] = {z0, z1};
#pragma unroll
            for (int a = 0; a < 2; a++)
#pragma unroll
                for (int b = 0; b < 2; b++)
#pragma unroll
                    for (int c = 0; c < 2; c++) {
                        unsigned long long wp = pack2(wx[a] * wy[b] * wz[c]);
                        const ulonglong2* g2 = (const ulonglong2*)(grid +
                            ((size_t)((zs[c] * NG + ys[b]) * NG + xs[a])) * NC);
#pragma unroll
                        for (int q = 0; q < 8; q++) {
                            ulonglong2 v = g2[q];
                            fma2(fa2[2 * q], wp, v.x);
                            fma2(fa2[2 * q + 1], wp, v.y);
                        }
                    }
#pragma unroll
            for (int q = 0; q < 16; q++) unpack2(fa2[q], feats[2 * q], feats[2 * q + 1]);
        }

        // trunk: e = relu(relu(feats@Wt1+bt1)@Wt2+bt2)
        float e1[NH];
        dense64p<NC>(feats, sm + OFF_WT1, sm + OFF_BT1, e1);
#pragma unroll
        for (int o = 0; o < NH; o++) e1[o] = frelu(e1[o]);
        float e[NH];
        dense64p<NH>(e1, sm + OFF_WT2, sm + OFF_BT2, e);
#pragma unroll
        for (int o = 0; o < NH; o++) e[o] = frelu(e[o]);

        // opacity head
        float h[NH];
        dense64p<NH>(e, sm + OFF_WO1, sm + OFF_BO1, h);
        float raw = sm[OFF_MISC];
#pragma unroll
        for (int i = 0; i < NH; i++) raw = fmaf(frelu(h[i]), sm[OFF_WO2 + i], raw);

        float density = (raw > 0.f) ? (raw + log1pf(expf(-raw))) : log1pf(expf(raw));
        float delta = (fa - nr) / (float)NS;
        float am = expf(-delta * density);   // 1 - alpha

        // color head
        __syncthreads();                      // sync2: OFF_RAY ready
#pragma unroll
        for (int i = 0; i < NH; i++) e[i] += sm[OFF_RAY + i];
        dense64p<NH>(e, sm + OFF_WC1, sm + OFF_BC1, h);
        float c0 = sm[OFF_MISC + 1], c1 = sm[OFF_MISC + 2], c2 = sm[OFF_MISC + 3];
#pragma unroll
        for (int i = 0; i < NH; i++) {
            float hv = frelu(h[i]);
            c0 = fmaf(hv, sm[OFF_WC2 + i * 3 + 0], c0);
            c1 = fmaf(hv, sm[OFF_WC2 + i * 3 + 1], c1);
            c2 = fmaf(hv, sm[OFF_WC2 + i * 3 + 2], c2);
        }
        c0 = 1.f / (1.f + expf(-c0));
        c1 = 1.f / (1.f + expf(-c1));
        c2 = 1.f / (1.f + expf(-c2));

        // ---- parallel transmittance scan (warp shuffle) ----
        float incl = am;
#pragma unroll
        for (int off = 1; off < 32; off <<= 1) {
            float n = __shfl_up_sync(0xffffffffu, incl, off);
            if (lane >= off) incl *= n;
        }
        float excl = __shfl_up_sync(0xffffffffu, incl, 1);
        if (lane == 0) excl = 1.f;
        if (lane == 31) sm[OFF_WTOT + warp] = incl;
        __syncthreads();                      // sync3: warp totals ready
        float w0 = sm[OFF_WTOT + 0], w1 = sm[OFF_WTOT + 1];
        float w2t = sm[OFF_WTOT + 2], w3 = sm[OFF_WTOT + 3];
        float pre = 1.f;
        if (warp > 0) pre *= w0;
        if (warp > 1) pre *= w1;
        if (warp > 2) pre *= w2t;
        float T = pre * excl;                 // transmittance before this sample
        float total = w0 * w1 * w2t * w3;     // trans[:, -1]
        float wgt = T * (1.f - am);

        float r0 = wgt * c0, r1 = wgt * c1, r2 = wgt * c2;
#pragma unroll
        for (int off = 16; off > 0; off >>= 1) {
            r0 += __shfl_down_sync(0xffffffffu, r0, off);
            r1 += __shfl_down_sync(0xffffffffu, r1, off);
            r2 += __shfl_down_sync(0xffffffffu, r2, off);
        }
        if (lane == 0) {
            sm[OFF_PART + warp * 3 + 0] = r0;
            sm[OFF_PART + warp * 3 + 1] = r1;
            sm[OFF_PART + warp * 3 + 2] = r2;
        }
        __syncthreads();                      // sync4: partials ready
        if (tid == 0) {
            float s0 = 0.f, s1 = 0.f, s2 = 0.f;
#pragma unroll
            for (int w = 0; w < 4; w++) {
                s0 += sm[OFF_PART + w * 3 + 0];
                s1 += sm[OFF_PART + w * 3 + 1];
                s2 += sm[OFF_PART + w * 3 + 2];
            }
            out[ray * 3 + 0] = s0;
            out[ray * 3 + 1] = s1;
            out[ray * 3 + 2] = s2;
            out[NRAYS * 3 + ray] = 1.f - total;   // mask
        }
    }
}

extern "C" void kernel_launch(void* const* d_in, const int* in_sizes, int n_in,
                              void* d_out, int out_size) {
    const float* origins    = (const float*)d_in[0];
    const float* directions = (const float*)d_in[1];
    const float* nearv      = (const float*)d_in[2];
    const float* farv       = (const float*)d_in[3];
    const float* grid       = (const float*)d_in[4];
    const float* Wr  = (const float*)d_in[5];
    const float* br  = (const float*)d_in[6];
    const float* Wt1 = (const float*)d_in[7];
    const float* bt1 = (const float*)d_in[8];
    const float* Wt2 = (const float*)d_in[9];
    const float* bt2 = (const float*)d_in[10];
    const float* Wo1 = (const float*)d_in[11];
    const float* bo1 = (const float*)d_in[12];
    const float* Wo2 = (const float*)d_in[13];
    const float* bo2 = (const float*)d_in[14];
    const float* Wc1 = (const float*)d_in[15];
    const float* bc1 = (const float*)d_in[16];
    const float* Wc2 = (const float*)d_in[17];
    const float* bc2 = (const float*)d_in[18];
    float* out = (float*)d_out;

    cudaFuncSetAttribute(lightplane_kernel,
                         cudaFuncAttributeMaxDynamicSharedMemorySize, SMEM_BYTES);
    lightplane_kernel<<<NRAYS / RPB, NS, SMEM_BYTES>>>(
        origins, directions, nearv, farv, grid,
        Wr, br, Wt1, bt1, Wt2, bt2, Wo1, bo1, Wo2, bo2,
        Wc1, bc1, Wc2, bc2, out);
}